// round 1
// baseline (speedup 1.0000x reference)
#include <cuda_runtime.h>
#include <cstdint>

#define NBOX 8192
#define CLS  81
#define NPAD 300
#define NWORDS (NBOX / 32)   // 256 suppression words

// scratch (no allocations allowed)
__device__ float g_sel[NBOX * 4];   // decoded argmax-class boxes (clipped)
__device__ float g_ms[NBOX];        // max score over classes 1..80

// ---------------------------------------------------------------------------
// Kernel 1: per-row argmax / max + bbox decode. One warp per row.
// ---------------------------------------------------------------------------
__global__ void decode_kernel(const float* __restrict__ meta,
                              const float* __restrict__ deltas,
                              const float* __restrict__ proposals,
                              const float* __restrict__ scores) {
    int row  = (int)((blockIdx.x * blockDim.x + threadIdx.x) >> 5);
    int lane = threadIdx.x & 31;
    if (row >= NBOX) return;

    const float* srow = scores + (size_t)row * CLS;
    float best = -1.0f;          // scores are in [0,1)
    int   bidx = 0x7FFFFFFF;
    float ms   = -1.0f;
    for (int j = lane; j < CLS; j += 32) {
        float v = srow[j];
        if (v > best) { best = v; bidx = j; }   // strict > keeps lowest idx in-lane
        if (j >= 1) ms = fmaxf(ms, v);
    }
    #pragma unroll
    for (int off = 16; off; off >>= 1) {
        float ov = __shfl_down_sync(0xffffffffu, best, off);
        int   oi = __shfl_down_sync(0xffffffffu, bidx, off);
        float om = __shfl_down_sync(0xffffffffu, ms,   off);
        if (ov > best || (ov == best && oi < bidx)) { best = ov; bidx = oi; }
        ms = fmaxf(ms, om);
    }

    if (lane == 0) {
        float scale = meta[2];
        const float* p = proposals + (size_t)row * 4;
        float x1 = p[0] / scale, y1 = p[1] / scale;
        float x2 = p[2] / scale, y2 = p[3] / scale;
        float w  = x2 - x1 + 1.0f, h = y2 - y1 + 1.0f;
        float cx = x1 + 0.5f * w,  cy = y1 + 0.5f * h;

        const float* d = deltas + (size_t)row * (4 * CLS) + 4 * bidx;
        float pcx = d[0] * w + cx;
        float pcy = d[1] * h + cy;
        float pw  = expf(d[2]) * w;
        float ph  = expf(d[3]) * h;

        float W1 = meta[1] - 1.0f;   // W - 1
        float H1 = meta[0] - 1.0f;   // H - 1
        float ox1 = fminf(fmaxf(pcx - 0.5f * pw, 0.0f), W1);
        float oy1 = fminf(fmaxf(pcy - 0.5f * ph, 0.0f), H1);
        float ox2 = fminf(fmaxf(pcx + 0.5f * pw, 0.0f), W1);
        float oy2 = fminf(fmaxf(pcy + 0.5f * ph, 0.0f), H1);

        float* sel = g_sel + (size_t)row * 4;
        sel[0] = ox1; sel[1] = oy1; sel[2] = ox2; sel[3] = oy2;
        g_ms[row] = ms;
    }
}

// ---------------------------------------------------------------------------
// Kernel 2: single-block fused  sort -> greedy NMS -> gather
//   smem layout (byte offsets):
//     [0,       131072)  float4 boxes[NBOX]     (sorted order)
//     [131072,  196608)  u64    keys[NBOX]      (score<<13 | (8191-idx))
//     [196608,  197632)  u32    sup[NWORDS]
//     [197632,  198832)  int    keep_list[NPAD]
//     [198832,  198848)  int    ctrl
// ---------------------------------------------------------------------------
#define SMEM_BYTES 198848

__global__ void __launch_bounds__(1024, 1)
nms_kernel(const float* __restrict__ scores, float* __restrict__ out) {
    const int tid = threadIdx.x;
    extern __shared__ unsigned char smem_raw[];
    float4*             boxes     = (float4*)(smem_raw);
    unsigned long long* keys      = (unsigned long long*)(smem_raw + 131072);
    unsigned int*       sup       = (unsigned int*)(smem_raw + 196608);
    int*                keep_list = (int*)(smem_raw + 197632);
    int*                ctrl      = (int*)(smem_raw + 198832);

    // --- load composite sort keys ---
    for (int i = tid; i < NBOX; i += 1024) {
        unsigned int sb = __float_as_uint(g_ms[i]);   // scores >= 0 -> bits monotonic
        keys[i] = ((unsigned long long)sb << 13) |
                  (unsigned long long)(8191 - i);      // tiebreak: lower idx first
    }
    __syncthreads();

    // --- bitonic sort, descending ---
    for (int k = 2; k <= NBOX; k <<= 1) {
        for (int j = k >> 1; j > 0; j >>= 1) {
            for (int i = tid; i < NBOX; i += 1024) {
                int ij = i ^ j;
                if (ij > i) {
                    unsigned long long a = keys[i], b = keys[ij];
                    bool desc = ((i & k) == 0);
                    if (desc ? (a < b) : (a > b)) { keys[i] = b; keys[ij] = a; }
                }
            }
            __syncthreads();
        }
    }

    // --- gather boxes in sorted order; clear suppression bitmask ---
    for (int i = tid; i < NBOX; i += 1024) {
        int orig = 8191 - (int)(keys[i] & 0x1FFFull);
        const float* s = g_sel + (size_t)orig * 4;
        boxes[i] = make_float4(s[0], s[1], s[2], s[3]);
    }
    for (int i = tid; i < NWORDS; i += 1024) sup[i] = 0u;
    __syncthreads();

    // --- greedy NMS: loop runs exactly num_kept (<=300) times ---
    int kept = 0;                 // identical across all threads (uniform loop)
    int cur  = 0;                 // thread 0 only
    const int warpid = tid >> 5, lane = tid & 31;

    while (true) {
        if (tid == 0) {
            int found = -1;
            int wi = cur >> 5;
            unsigned int m = 0xFFFFFFFFu << (cur & 31);
            while (wi < NWORDS) {
                unsigned int avail = ~sup[wi] & m;
                if (avail) { found = (wi << 5) + __ffs(avail) - 1; break; }
                wi++; m = 0xFFFFFFFFu;
            }
            ctrl[0] = found;
        }
        __syncthreads();
        int i = ctrl[0];
        if (i < 0) break;

        if (tid == 0) { keep_list[kept] = i; cur = i + 1; }

        float4 bi = boxes[i];
        float areai = fmaxf(bi.z - bi.x, 0.0f) * fmaxf(bi.w - bi.y, 0.0f);
        int wstart = (i + 1) >> 5;
        for (int w = wstart + warpid; w < NWORDS; w += 32) {
            unsigned int already = sup[w];       // broadcast read
            int j = (w << 5) + lane;
            bool sflag = false;
            if (j > i && !((already >> lane) & 1u)) {
                float4 bj = boxes[j];
                float xx1 = fmaxf(bi.x, bj.x), yy1 = fmaxf(bi.y, bj.y);
                float xx2 = fminf(bi.z, bj.z), yy2 = fminf(bi.w, bj.w);
                float iw  = fmaxf(xx2 - xx1, 0.0f), ih = fmaxf(yy2 - yy1, 0.0f);
                float inter = iw * ih;
                float areaj = fmaxf(bj.z - bj.x, 0.0f) * fmaxf(bj.w - bj.y, 0.0f);
                float iou   = inter / (areai + areaj - inter + 1e-8f);
                sflag = iou > 0.5f;
            }
            unsigned int bal = __ballot_sync(0xffffffffu, sflag);
            if (lane == 0 && bal) atomicOr(&sup[w], bal);
        }
        __syncthreads();
        kept++;
        if (kept >= NPAD) break;
    }
    __syncthreads();
    int nk = kept;

    // --- outputs: boxes (300*4) then scores (300*81); zero-fill invalid rows ---
    for (int idx = tid; idx < NPAD * 4; idx += 1024) {
        int r = idx >> 2, c = idx & 3;
        float v = 0.0f;
        if (r < nk) {
            float4 b = boxes[keep_list[r]];
            v = (c == 0) ? b.x : (c == 1) ? b.y : (c == 2) ? b.z : b.w;
        }
        out[idx] = v;
    }
    for (int idx = tid; idx < NPAD * CLS; idx += 1024) {
        int r = idx / CLS, c = idx - r * CLS;
        float v = 0.0f;
        if (r < nk) {
            int srt  = keep_list[r];
            int orig = 8191 - (int)(keys[srt] & 0x1FFFull);
            v = scores[(size_t)orig * CLS + c];
        }
        out[NPAD * 4 + idx] = v;
    }
}

// ---------------------------------------------------------------------------
extern "C" void kernel_launch(void* const* d_in, const int* in_sizes, int n_in,
                              void* d_out, int out_size) {
    const float* meta      = (const float*)d_in[0];
    const float* deltas    = (const float*)d_in[1];
    const float* proposals = (const float*)d_in[2];
    const float* scores    = (const float*)d_in[3];
    float* out = (float*)d_out;

    // one warp per row: 8192 warps -> 1024 blocks x 256 threads
    decode_kernel<<<NBOX / 8, 256>>>(meta, deltas, proposals, scores);

    cudaFuncSetAttribute(nms_kernel,
                         cudaFuncAttributeMaxDynamicSharedMemorySize, SMEM_BYTES);
    nms_kernel<<<1, 1024, SMEM_BYTES>>>(scores, out);
}

// round 2
// speedup vs baseline: 3.4614x; 3.4614x over previous
#include <cuda_runtime.h>
#include <cstdint>

#define NBOX   8192
#define CLS    81
#define NPAD   300
#define NWORDS (NBOX / 32)      // 256 suppression words

// ------------------------- device scratch (static, no allocs) --------------
__device__ float4   g_selv[NBOX];            // decoded argmax-class boxes
__device__ float    g_ms[NBOX];              // max score over classes 1..80
__device__ int      g_order[NBOX];           // sorted original indices
__device__ unsigned g_mask[(size_t)NBOX * NWORDS];   // 8 MB IoU>0.5 bitmatrix

// ---------------------------------------------------------------------------
// Kernel 1: per-row argmax / max + bbox decode. One warp per row.
// ---------------------------------------------------------------------------
__global__ void decode_kernel(const float* __restrict__ meta,
                              const float* __restrict__ deltas,
                              const float* __restrict__ proposals,
                              const float* __restrict__ scores) {
    int row  = (int)((blockIdx.x * blockDim.x + threadIdx.x) >> 5);
    int lane = threadIdx.x & 31;
    if (row >= NBOX) return;

    const float* srow = scores + (size_t)row * CLS;
    float best = -1.0f;
    int   bidx = 0x7FFFFFFF;
    float ms   = -1.0f;
    for (int j = lane; j < CLS; j += 32) {
        float v = srow[j];
        if (v > best) { best = v; bidx = j; }
        if (j >= 1) ms = fmaxf(ms, v);
    }
    #pragma unroll
    for (int off = 16; off; off >>= 1) {
        float ov = __shfl_down_sync(0xffffffffu, best, off);
        int   oi = __shfl_down_sync(0xffffffffu, bidx, off);
        float om = __shfl_down_sync(0xffffffffu, ms,   off);
        if (ov > best || (ov == best && oi < bidx)) { best = ov; bidx = oi; }
        ms = fmaxf(ms, om);
    }

    if (lane == 0) {
        float scale = meta[2];
        const float* p = proposals + (size_t)row * 4;
        float x1 = p[0] / scale, y1 = p[1] / scale;
        float x2 = p[2] / scale, y2 = p[3] / scale;
        float w  = x2 - x1 + 1.0f, h = y2 - y1 + 1.0f;
        float cx = x1 + 0.5f * w,  cy = y1 + 0.5f * h;

        const float* d = deltas + (size_t)row * (4 * CLS) + 4 * bidx;
        float pcx = d[0] * w + cx;
        float pcy = d[1] * h + cy;
        float pw  = expf(d[2]) * w;
        float ph  = expf(d[3]) * h;

        float W1 = meta[1] - 1.0f;
        float H1 = meta[0] - 1.0f;
        float ox1 = fminf(fmaxf(pcx - 0.5f * pw, 0.0f), W1);
        float oy1 = fminf(fmaxf(pcy - 0.5f * ph, 0.0f), H1);
        float ox2 = fminf(fmaxf(pcx + 0.5f * pw, 0.0f), W1);
        float oy2 = fminf(fmaxf(pcy + 0.5f * ph, 0.0f), H1);

        g_selv[row] = make_float4(ox1, oy1, ox2, oy2);
        g_ms[row]   = ms;
    }
}

// ---------------------------------------------------------------------------
// Kernel 2 (fused): block 2048 = bitonic sort of composite keys;
//                   blocks 0..2047 = full 8192x8192 IoU>0.5 bitmask.
// Mask tile: 32 rows x 1024 cols per block (256 row-blocks x 8 col-blocks).
// ---------------------------------------------------------------------------
#define SORT_SMEM 65536   // 8192 * u64 keys

__global__ void __launch_bounds__(256)
sortmask_kernel() {
    extern __shared__ unsigned char dsm[];
    const int tid = threadIdx.x;

    if (blockIdx.x == 2048) {
        // ------------------- bitonic sort, descending ---------------------
        unsigned long long* keys = (unsigned long long*)dsm;
        for (int i = tid; i < NBOX; i += 256) {
            unsigned int sb = __float_as_uint(g_ms[i]);   // scores >= 0
            keys[i] = ((unsigned long long)sb << 13) |
                      (unsigned long long)(8191 - i);     // stable tiebreak
        }
        __syncthreads();
        for (int k = 2; k <= NBOX; k <<= 1) {
            for (int j = k >> 1; j > 0; j >>= 1) {
                for (int i = tid; i < NBOX; i += 256) {
                    int ij = i ^ j;
                    if (ij > i) {
                        unsigned long long a = keys[i], b = keys[ij];
                        bool desc = ((i & k) == 0);
                        if (desc ? (a < b) : (a > b)) { keys[i] = b; keys[ij] = a; }
                    }
                }
                __syncthreads();
            }
        }
        for (int i = tid; i < NBOX; i += 256)
            g_order[i] = 8191 - (int)(keys[i] & 0x1FFFull);
    } else {
        // ------------------- IoU mask tile --------------------------------
        float4* rb  = (float4*)(dsm);             // 32 row boxes       (512 B)
        float*  ra  = (float*) (dsm + 512);       // 32 row areas       (128 B)
        float4* cbT = (float4*)(dsm + 1024);      // transposed col boxes, stride 33
        float*  caT = (float*) (dsm + 1024 + 32 * 33 * 16); // col areas, stride 33

        int m       = blockIdx.x;
        int rowbase = (m & 255) * 32;
        int colbase = (m >> 8) * 1024;

        if (tid < 32) {
            float4 b = g_selv[rowbase + tid];
            rb[tid] = b;
            ra[tid] = fmaxf(b.z - b.x, 0.0f) * fmaxf(b.w - b.y, 0.0f);
        }
        for (int jj = tid; jj < 1024; jj += 256) {
            float4 b = g_selv[colbase + jj];
            int w = jj >> 5, bb = jj & 31;
            cbT[bb * 33 + w] = b;
            caT[bb * 33 + w] = fmaxf(b.z - b.x, 0.0f) * fmaxf(b.w - b.y, 0.0f);
        }
        __syncthreads();

        #pragma unroll
        for (int k = 0; k < 4; k++) {
            int r = (tid >> 5) + k * 8;   // row within tile
            int w = tid & 31;             // word (32 cols) within tile
            float4 bi = rb[r];
            float  si = ra[r] + 1e-8f;
            unsigned bits = 0;
            #pragma unroll
            for (int b = 0; b < 32; b++) {
                float4 bj = cbT[b * 33 + w];
                float  aj = caT[b * 33 + w];
                float xx1 = fmaxf(bi.x, bj.x), yy1 = fmaxf(bi.y, bj.y);
                float xx2 = fminf(bi.z, bj.z), yy2 = fminf(bi.w, bj.w);
                float iw  = fmaxf(xx2 - xx1, 0.0f);
                float ih  = fmaxf(yy2 - yy1, 0.0f);
                float inter = iw * ih;
                // iou > 0.5  <=>  3*inter > area_i + area_j + 1e-8
                if (3.0f * inter > si + aj) bits |= (1u << b);
            }
            g_mask[(size_t)(rowbase + r) * NWORDS + (colbase >> 5) + w] = bits;
        }
    }
}

// ---------------------------------------------------------------------------
// Kernel 3: serial greedy scan over precomputed mask (1 block),
//           chunked 32 sorted positions at a time, then output write.
// ---------------------------------------------------------------------------
__global__ void __launch_bounds__(256)
scan_kernel(const float* __restrict__ scores, float* __restrict__ out) {
    __shared__ int      s_order[NBOX];     // 32 KB
    __shared__ unsigned sup[NWORDS];       // suppression bits, original space
    __shared__ unsigned confs[32];
    __shared__ int      s_keep[NPAD];
    __shared__ int      s_nk;

    const int tid = threadIdx.x;
    for (int i = tid; i < NBOX; i += 256) s_order[i] = g_order[i];
    for (int i = tid; i < NWORDS; i += 256) sup[i] = 0u;
    __syncthreads();

    if (tid < 32) {
        const int lane = tid;
        int kept = 0;
        for (int c = 0; c < NBOX / 32 && kept < NPAD; c++) {
            int o = s_order[c * 32 + lane];
            __syncwarp();
            bool alive = !((sup[o >> 5] >> (o & 31)) & 1u);
            unsigned am = __ballot_sync(0xffffffffu, alive);
            if (!am) continue;

            // pairwise conflict matrix for this chunk (lane l = row owner)
            const unsigned* myrow = g_mask + (size_t)o * NWORDS;
            unsigned conf = 0;
            #pragma unroll
            for (int l2 = 0; l2 < 32; l2++) {
                int o2 = __shfl_sync(0xffffffffu, o, l2);
                unsigned wrd = __ldg(&myrow[o2 >> 5]);
                conf |= ((wrd >> (o2 & 31)) & 1u) << l2;
            }
            confs[lane] = conf;
            __syncwarp();

            // serial greedy resolution within chunk (uniform across lanes)
            unsigned keepm = 0;
            while (am) {
                int l = __ffs(am) - 1;
                keepm |= 1u << l;
                am &= ~confs[l];
                am &= ~(1u << l);
            }

            // OR kept rows into suppression mask (8 words per lane)
            unsigned acc[8];
            #pragma unroll
            for (int q = 0; q < 8; q++) acc[q] = 0u;
            unsigned km = keepm;
            while (km) {
                int l = __ffs(km) - 1; km &= km - 1;
                int ko = __shfl_sync(0xffffffffu, o, l);
                const unsigned* kr = g_mask + (size_t)ko * NWORDS;
                #pragma unroll
                for (int q = 0; q < 8; q++) acc[q] |= __ldg(&kr[q * 32 + lane]);
            }
            #pragma unroll
            for (int q = 0; q < 8; q++) sup[q * 32 + lane] |= acc[q];

            // append kept (sorted order preserved: ascending lane)
            km = keepm;
            while (km && kept < NPAD) {
                int l = __ffs(km) - 1; km &= km - 1;
                int ko = __shfl_sync(0xffffffffu, o, l);
                if (lane == 0) s_keep[kept] = ko;
                kept++;
            }
            __syncwarp();
        }
        if (lane == 0) s_nk = kept;
    }
    __syncthreads();
    const int nk = s_nk;

    // outputs: boxes (300*4) then scores (300*81); zero-fill invalid rows
    const float* self = (const float*)g_selv;
    for (int idx = tid; idx < NPAD * 4; idx += 256) {
        int r = idx >> 2, cc = idx & 3;
        out[idx] = (r < nk) ? self[(size_t)s_keep[r] * 4 + cc] : 0.0f;
    }
    for (int idx = tid; idx < NPAD * CLS; idx += 256) {
        int r = idx / CLS, cc = idx - r * CLS;
        out[NPAD * 4 + idx] =
            (r < nk) ? scores[(size_t)s_keep[r] * CLS + cc] : 0.0f;
    }
}

// ---------------------------------------------------------------------------
extern "C" void kernel_launch(void* const* d_in, const int* in_sizes, int n_in,
                              void* d_out, int out_size) {
    const float* meta      = (const float*)d_in[0];
    const float* deltas    = (const float*)d_in[1];
    const float* proposals = (const float*)d_in[2];
    const float* scores    = (const float*)d_in[3];
    float* out = (float*)d_out;

    decode_kernel<<<NBOX / 8, 256>>>(meta, deltas, proposals, scores);

    cudaFuncSetAttribute(sortmask_kernel,
                         cudaFuncAttributeMaxDynamicSharedMemorySize, SORT_SMEM);
    sortmask_kernel<<<2049, 256, SORT_SMEM>>>();

    scan_kernel<<<1, 256>>>(scores, out);
}

// round 3
// speedup vs baseline: 6.4180x; 1.8542x over previous
#include <cuda_runtime.h>
#include <cstdint>

#define NBOX   8192
#define CLS    81
#define NPAD   300
#define NWORDS (NBOX / 32)      // 256 suppression words

// ------------------------- device scratch (static, no allocs) --------------
__device__ float4             g_selv[NBOX];          // decoded boxes
__device__ unsigned long long g_key[NBOX];           // composite sort keys
__device__ int                g_order[NBOX];         // sorted original indices
__device__ unsigned           g_mask[(size_t)NBOX * NWORDS]; // 8 MB IoU matrix

// ---------------------------------------------------------------------------
// Kernel 1: per-row argmax / max + bbox decode + sort-key build. 1 warp/row.
// ---------------------------------------------------------------------------
__global__ void decode_kernel(const float* __restrict__ meta,
                              const float* __restrict__ deltas,
                              const float* __restrict__ proposals,
                              const float* __restrict__ scores) {
    int row  = (int)((blockIdx.x * blockDim.x + threadIdx.x) >> 5);
    int lane = threadIdx.x & 31;
    if (row >= NBOX) return;

    const float* srow = scores + (size_t)row * CLS;
    float best = -1.0f;
    int   bidx = 0x7FFFFFFF;
    float ms   = -1.0f;
    for (int j = lane; j < CLS; j += 32) {
        float v = srow[j];
        if (v > best) { best = v; bidx = j; }
        if (j >= 1) ms = fmaxf(ms, v);
    }
    #pragma unroll
    for (int off = 16; off; off >>= 1) {
        float ov = __shfl_down_sync(0xffffffffu, best, off);
        int   oi = __shfl_down_sync(0xffffffffu, bidx, off);
        float om = __shfl_down_sync(0xffffffffu, ms,   off);
        if (ov > best || (ov == best && oi < bidx)) { best = ov; bidx = oi; }
        ms = fmaxf(ms, om);
    }

    if (lane == 0) {
        float scale = meta[2];
        const float* p = proposals + (size_t)row * 4;
        float x1 = p[0] / scale, y1 = p[1] / scale;
        float x2 = p[2] / scale, y2 = p[3] / scale;
        float w  = x2 - x1 + 1.0f, h = y2 - y1 + 1.0f;
        float cx = x1 + 0.5f * w,  cy = y1 + 0.5f * h;

        const float* d = deltas + (size_t)row * (4 * CLS) + 4 * bidx;
        float pcx = d[0] * w + cx;
        float pcy = d[1] * h + cy;
        float pw  = expf(d[2]) * w;
        float ph  = expf(d[3]) * h;

        float W1 = meta[1] - 1.0f;
        float H1 = meta[0] - 1.0f;
        float ox1 = fminf(fmaxf(pcx - 0.5f * pw, 0.0f), W1);
        float oy1 = fminf(fmaxf(pcy - 0.5f * ph, 0.0f), H1);
        float ox2 = fminf(fmaxf(pcx + 0.5f * pw, 0.0f), W1);
        float oy2 = fminf(fmaxf(pcy + 0.5f * ph, 0.0f), H1);

        g_selv[row] = make_float4(ox1, oy1, ox2, oy2);
        // composite key: (score_bits << 13) | (8191 - idx) -> all keys distinct
        unsigned int sb = __float_as_uint(ms);          // scores >= 0
        g_key[row] = ((unsigned long long)sb << 13) |
                     (unsigned long long)(8191 - row);
    }
}

// ---------------------------------------------------------------------------
// Kernel 2 (fused, 2304 blocks x 256):
//   blocks    0..2047 : 32x1024 tiles of the 8192x8192 IoU>0.5 bitmask
//   blocks 2048..2303 : rank-by-counting sort (32 rows/block)
// ---------------------------------------------------------------------------
#define K2_SMEM 65536   // rank blocks cache all 8192 u64 keys

__global__ void __launch_bounds__(256)
rankmask_kernel() {
    extern __shared__ unsigned char dsm[];
    const int tid = threadIdx.x;

    if (blockIdx.x >= 2048) {
        // ------------------- rank by counting (replaces sort) -------------
        unsigned long long* keys = (unsigned long long*)dsm;
        for (int i = tid; i < NBOX; i += 256) keys[i] = g_key[i];
        __syncthreads();

        const int warp = tid >> 5, lane = tid & 31;
        const int row0 = (blockIdx.x - 2048) * 32 + warp * 4;

        unsigned long long rk0 = keys[row0 + 0];
        unsigned long long rk1 = keys[row0 + 1];
        unsigned long long rk2 = keys[row0 + 2];
        unsigned long long rk3 = keys[row0 + 3];
        int c0 = 0, c1 = 0, c2 = 0, c3 = 0;

        #pragma unroll 4
        for (int c = lane; c < NBOX; c += 32) {
            unsigned long long kc = keys[c];
            c0 += (kc > rk0);
            c1 += (kc > rk1);
            c2 += (kc > rk2);
            c3 += (kc > rk3);
        }
        #pragma unroll
        for (int off = 16; off; off >>= 1) {
            c0 += __shfl_down_sync(0xffffffffu, c0, off);
            c1 += __shfl_down_sync(0xffffffffu, c1, off);
            c2 += __shfl_down_sync(0xffffffffu, c2, off);
            c3 += __shfl_down_sync(0xffffffffu, c3, off);
        }
        if (lane == 0) {            // keys distinct -> ranks form a permutation
            g_order[c0] = row0 + 0;
            g_order[c1] = row0 + 1;
            g_order[c2] = row0 + 2;
            g_order[c3] = row0 + 3;
        }
    } else {
        // ------------------- IoU mask tile --------------------------------
        float4* rb  = (float4*)(dsm);             // 32 row boxes
        float*  ra  = (float*) (dsm + 512);       // 32 row areas
        float4* cbT = (float4*)(dsm + 1024);      // transposed col boxes (stride 33)
        float*  caT = (float*) (dsm + 1024 + 32 * 33 * 16);

        int m       = blockIdx.x;
        int rowbase = (m & 255) * 32;
        int colbase = (m >> 8) * 1024;

        if (tid < 32) {
            float4 b = g_selv[rowbase + tid];
            rb[tid] = b;
            ra[tid] = fmaxf(b.z - b.x, 0.0f) * fmaxf(b.w - b.y, 0.0f);
        }
        for (int jj = tid; jj < 1024; jj += 256) {
            float4 b = g_selv[colbase + jj];
            int w = jj >> 5, bb = jj & 31;
            cbT[bb * 33 + w] = b;
            caT[bb * 33 + w] = fmaxf(b.z - b.x, 0.0f) * fmaxf(b.w - b.y, 0.0f);
        }
        __syncthreads();

        #pragma unroll
        for (int k = 0; k < 4; k++) {
            int r = (tid >> 5) + k * 8;
            int w = tid & 31;
            float4 bi = rb[r];
            float  si = ra[r] + 1e-8f;
            unsigned bits = 0;
            #pragma unroll
            for (int b = 0; b < 32; b++) {
                float4 bj = cbT[b * 33 + w];
                float  aj = caT[b * 33 + w];
                float xx1 = fmaxf(bi.x, bj.x), yy1 = fmaxf(bi.y, bj.y);
                float xx2 = fminf(bi.z, bj.z), yy2 = fminf(bi.w, bj.w);
                float iw  = fmaxf(xx2 - xx1, 0.0f);
                float ih  = fmaxf(yy2 - yy1, 0.0f);
                float inter = iw * ih;
                // iou > 0.5  <=>  3*inter > area_i + area_j + 1e-8
                if (3.0f * inter > si + aj) bits |= (1u << b);
            }
            g_mask[(size_t)(rowbase + r) * NWORDS + (colbase >> 5) + w] = bits;
        }
    }
}

// ---------------------------------------------------------------------------
// Kernel 3: serial greedy scan over precomputed mask (1 block) + output.
// ---------------------------------------------------------------------------
__global__ void __launch_bounds__(256)
scan_kernel(const float* __restrict__ scores, float* __restrict__ out) {
    __shared__ int      s_order[NBOX];
    __shared__ unsigned sup[NWORDS];
    __shared__ unsigned confs[32];
    __shared__ int      s_keep[NPAD];
    __shared__ int      s_nk;

    const int tid = threadIdx.x;
    for (int i = tid; i < NBOX; i += 256) s_order[i] = g_order[i];
    for (int i = tid; i < NWORDS; i += 256) sup[i] = 0u;
    __syncthreads();

    if (tid < 32) {
        const int lane = tid;
        int kept = 0;
        for (int c = 0; c < NBOX / 32 && kept < NPAD; c++) {
            int o = s_order[c * 32 + lane];
            __syncwarp();
            bool alive = !((sup[o >> 5] >> (o & 31)) & 1u);
            unsigned am = __ballot_sync(0xffffffffu, alive);
            if (!am) continue;

            const unsigned* myrow = g_mask + (size_t)o * NWORDS;
            unsigned conf = 0;
            #pragma unroll
            for (int l2 = 0; l2 < 32; l2++) {
                int o2 = __shfl_sync(0xffffffffu, o, l2);
                unsigned wrd = __ldg(&myrow[o2 >> 5]);
                conf |= ((wrd >> (o2 & 31)) & 1u) << l2;
            }
            confs[lane] = conf;
            __syncwarp();

            unsigned keepm = 0;
            while (am) {
                int l = __ffs(am) - 1;
                keepm |= 1u << l;
                am &= ~confs[l];
                am &= ~(1u << l);
            }

            unsigned acc[8];
            #pragma unroll
            for (int q = 0; q < 8; q++) acc[q] = 0u;
            unsigned km = keepm;
            while (km) {
                int l = __ffs(km) - 1; km &= km - 1;
                int ko = __shfl_sync(0xffffffffu, o, l);
                const unsigned* kr = g_mask + (size_t)ko * NWORDS;
                #pragma unroll
                for (int q = 0; q < 8; q++) acc[q] |= __ldg(&kr[q * 32 + lane]);
            }
            #pragma unroll
            for (int q = 0; q < 8; q++) sup[q * 32 + lane] |= acc[q];

            km = keepm;
            while (km && kept < NPAD) {
                int l = __ffs(km) - 1; km &= km - 1;
                int ko = __shfl_sync(0xffffffffu, o, l);
                if (lane == 0) s_keep[kept] = ko;
                kept++;
            }
            __syncwarp();
        }
        if (lane == 0) s_nk = kept;
    }
    __syncthreads();
    const int nk = s_nk;

    const float* self = (const float*)g_selv;
    for (int idx = tid; idx < NPAD * 4; idx += 256) {
        int r = idx >> 2, cc = idx & 3;
        out[idx] = (r < nk) ? self[(size_t)s_keep[r] * 4 + cc] : 0.0f;
    }
    for (int idx = tid; idx < NPAD * CLS; idx += 256) {
        int r = idx / CLS, cc = idx - r * CLS;
        out[NPAD * 4 + idx] =
            (r < nk) ? scores[(size_t)s_keep[r] * CLS + cc] : 0.0f;
    }
}

// ---------------------------------------------------------------------------
extern "C" void kernel_launch(void* const* d_in, const int* in_sizes, int n_in,
                              void* d_out, int out_size) {
    const float* meta      = (const float*)d_in[0];
    const float* deltas    = (const float*)d_in[1];
    const float* proposals = (const float*)d_in[2];
    const float* scores    = (const float*)d_in[3];
    float* out = (float*)d_out;

    decode_kernel<<<NBOX / 8, 256>>>(meta, deltas, proposals, scores);

    cudaFuncSetAttribute(rankmask_kernel,
                         cudaFuncAttributeMaxDynamicSharedMemorySize, K2_SMEM);
    rankmask_kernel<<<2304, 256, K2_SMEM>>>();

    scan_kernel<<<1, 256>>>(scores, out);
}

// round 4
// speedup vs baseline: 6.7325x; 1.0490x over previous
#include <cuda_runtime.h>
#include <cstdint>

#define NBOX   8192
#define CLS    81
#define NPAD   300
#define NWORDS (NBOX / 32)      // 256 words per mask row

// ------------------------- device scratch (static, no allocs) --------------
__device__ float4             g_selv[NBOX];     // decoded boxes (orig order)
__device__ unsigned long long g_key[NBOX];      // composite sort keys
__device__ float4             g_sbox[NBOX];     // boxes in sorted order
__device__ float              g_sarea[NBOX];    // areas in sorted order
__device__ int                g_orig[NBOX];     // sorted pos -> original idx
__device__ unsigned           g_masks[(size_t)NBOX * NWORDS]; // sorted-space IoU>0.5

// ---------------------------------------------------------------------------
// Kernel 1: per-row argmax / max + bbox decode + sort-key build. 1 warp/row.
// ---------------------------------------------------------------------------
__global__ void decode_kernel(const float* __restrict__ meta,
                              const float* __restrict__ deltas,
                              const float* __restrict__ proposals,
                              const float* __restrict__ scores) {
    int row  = (int)((blockIdx.x * blockDim.x + threadIdx.x) >> 5);
    int lane = threadIdx.x & 31;
    if (row >= NBOX) return;

    const float* srow = scores + (size_t)row * CLS;
    float best = -1.0f;
    int   bidx = 0x7FFFFFFF;
    float ms   = -1.0f;
    for (int j = lane; j < CLS; j += 32) {
        float v = srow[j];
        if (v > best) { best = v; bidx = j; }
        if (j >= 1) ms = fmaxf(ms, v);
    }
    #pragma unroll
    for (int off = 16; off; off >>= 1) {
        float ov = __shfl_down_sync(0xffffffffu, best, off);
        int   oi = __shfl_down_sync(0xffffffffu, bidx, off);
        float om = __shfl_down_sync(0xffffffffu, ms,   off);
        if (ov > best || (ov == best && oi < bidx)) { best = ov; bidx = oi; }
        ms = fmaxf(ms, om);
    }

    if (lane == 0) {
        float scale = meta[2];
        const float* p = proposals + (size_t)row * 4;
        float x1 = p[0] / scale, y1 = p[1] / scale;
        float x2 = p[2] / scale, y2 = p[3] / scale;
        float w  = x2 - x1 + 1.0f, h = y2 - y1 + 1.0f;
        float cx = x1 + 0.5f * w,  cy = y1 + 0.5f * h;

        const float* d = deltas + (size_t)row * (4 * CLS) + 4 * bidx;
        float pcx = d[0] * w + cx;
        float pcy = d[1] * h + cy;
        float pw  = expf(d[2]) * w;
        float ph  = expf(d[3]) * h;

        float W1 = meta[1] - 1.0f;
        float H1 = meta[0] - 1.0f;
        float ox1 = fminf(fmaxf(pcx - 0.5f * pw, 0.0f), W1);
        float oy1 = fminf(fmaxf(pcy - 0.5f * ph, 0.0f), H1);
        float ox2 = fminf(fmaxf(pcx + 0.5f * pw, 0.0f), W1);
        float oy2 = fminf(fmaxf(pcy + 0.5f * ph, 0.0f), H1);

        g_selv[row] = make_float4(ox1, oy1, ox2, oy2);
        unsigned int sb = __float_as_uint(ms);   // scores >= 0 -> monotonic bits
        g_key[row] = ((unsigned long long)sb << 13) |
                     (unsigned long long)(8191 - row);   // all keys distinct
    }
}

// ---------------------------------------------------------------------------
// Kernel 2: rank-by-counting (keys distinct -> rank is a permutation),
//           scatter boxes/areas/orig-idx into sorted order. 256 blocks.
// ---------------------------------------------------------------------------
__global__ void __launch_bounds__(256)
rank_kernel() {
    extern __shared__ unsigned long long keys[];   // 64 KB
    const int tid = threadIdx.x;
    for (int i = tid; i < NBOX; i += 256) keys[i] = g_key[i];
    __syncthreads();

    const int warp = tid >> 5, lane = tid & 31;
    const int row0 = blockIdx.x * 32 + warp * 4;

    unsigned long long rk0 = keys[row0 + 0];
    unsigned long long rk1 = keys[row0 + 1];
    unsigned long long rk2 = keys[row0 + 2];
    unsigned long long rk3 = keys[row0 + 3];
    int c0 = 0, c1 = 0, c2 = 0, c3 = 0;

    #pragma unroll 4
    for (int c = lane; c < NBOX; c += 32) {
        unsigned long long kc = keys[c];
        c0 += (kc > rk0);
        c1 += (kc > rk1);
        c2 += (kc > rk2);
        c3 += (kc > rk3);
    }
    #pragma unroll
    for (int off = 16; off; off >>= 1) {
        c0 += __shfl_down_sync(0xffffffffu, c0, off);
        c1 += __shfl_down_sync(0xffffffffu, c1, off);
        c2 += __shfl_down_sync(0xffffffffu, c2, off);
        c3 += __shfl_down_sync(0xffffffffu, c3, off);
    }
    if (lane == 0) {
        int rr[4] = {c0, c1, c2, c3};
        #pragma unroll
        for (int q = 0; q < 4; q++) {
            int i = row0 + q, r = rr[q];
            float4 b = g_selv[i];
            g_sbox[r]  = b;
            g_sarea[r] = fmaxf(b.z - b.x, 0.0f) * fmaxf(b.w - b.y, 0.0f);
            g_orig[r]  = i;
        }
    }
}

// ---------------------------------------------------------------------------
// Kernel 3: sorted-space IoU>0.5 bitmask, upper triangle only.
// 2048 blocks; tile = 32 rows x 1024 cols; block exits if wholly below diag.
// ---------------------------------------------------------------------------
__global__ void __launch_bounds__(256)
mask_kernel() {
    __shared__ float4 rbs[32];
    __shared__ float  ras[32];
    __shared__ float4 cbT[32 * 33];      // [bit][word], padded stride 33
    __shared__ float  caT[32 * 33];

    const int m  = blockIdx.x;
    const int rb = m & 255;              // row block (32 rows)
    const int cb = m >> 8;               // col block (1024 cols)
    if (cb < (rb >> 5)) return;          // strictly below diagonal band

    const int rowbase = rb * 32;
    const int colbase = cb * 1024;
    const int tid = threadIdx.x;

    if (tid < 32) {
        rbs[tid] = g_sbox[rowbase + tid];
        ras[tid] = g_sarea[rowbase + tid];
    }
    for (int jj = tid; jj < 1024; jj += 256) {
        int w = jj >> 5, bb = jj & 31;
        cbT[bb * 33 + w] = g_sbox[colbase + jj];
        caT[bb * 33 + w] = g_sarea[colbase + jj];
    }
    __syncthreads();

    const int r0 = tid >> 5;             // 0..7 ; rows r0, r0+8, r0+16, r0+24
    const int w  = tid & 31;             // word within tile
    float4 bi[4];
    float  si[4];
    #pragma unroll
    for (int k = 0; k < 4; k++) {
        bi[k] = rbs[r0 + 8 * k];
        si[k] = ras[r0 + 8 * k] + 1e-8f;
    }
    unsigned bits0 = 0, bits1 = 0, bits2 = 0, bits3 = 0;

    #pragma unroll
    for (int b = 0; b < 32; b++) {
        float4 bj = cbT[b * 33 + w];
        float  aj = caT[b * 33 + w];
        #pragma unroll
        for (int k = 0; k < 4; k++) {
            float xx1 = fmaxf(bi[k].x, bj.x), yy1 = fmaxf(bi[k].y, bj.y);
            float xx2 = fminf(bi[k].z, bj.z), yy2 = fminf(bi[k].w, bj.w);
            float iw  = fmaxf(xx2 - xx1, 0.0f);
            float ih  = fmaxf(yy2 - yy1, 0.0f);
            float inter = iw * ih;
            // iou > 0.5  <=>  3*inter > area_i + area_j + 1e-8
            unsigned p = (3.0f * inter > si[k] + aj) ? (1u << b) : 0u;
            if (k == 0) bits0 |= p;
            else if (k == 1) bits1 |= p;
            else if (k == 2) bits2 |= p;
            else bits3 |= p;
        }
    }
    size_t base = (size_t)rowbase * NWORDS + (size_t)cb * 32 + w;
    g_masks[base + (size_t)(r0 +  0) * NWORDS] = bits0;
    g_masks[base + (size_t)(r0 +  8) * NWORDS] = bits1;
    g_masks[base + (size_t)(r0 + 16) * NWORDS] = bits2;
    g_masks[base + (size_t)(r0 + 24) * NWORDS] = bits3;
}

// ---------------------------------------------------------------------------
// Kernel 4: greedy scan in sorted space (1 block, 256 threads) + output.
// ---------------------------------------------------------------------------
__global__ void __launch_bounds__(256)
scan_kernel(const float* __restrict__ scores, float* __restrict__ out) {
    __shared__ unsigned sup_s[NWORDS];   // suppression bits, sorted space
    __shared__ unsigned keepm_s;
    __shared__ int      s_keep[NPAD];    // kept sorted positions (ascending)
    __shared__ int      s_kept;

    const int tid = threadIdx.x;
    sup_s[tid] = 0u;
    if (tid == 0) s_kept = 0;
    __syncthreads();

    for (int c = 0; c < NWORDS; c++) {
        if (tid < 32) {
            unsigned avail = 0;
            if (tid == 0) avail = ~sup_s[c];
            avail = __shfl_sync(0xffffffffu, avail, 0);

            // conflict word: row = sorted pos (c*32+lane), col word = c
            unsigned conf = __ldg(&g_masks[(size_t)(c * 32 + tid) * NWORDS + c]);

            unsigned am = avail, keepm = 0;
            while (am) {
                int l = __ffs(am) - 1;
                keepm |= 1u << l;
                unsigned cl = __shfl_sync(0xffffffffu, conf, l);
                am &= ~cl;
                am &= ~(1u << l);
            }
            if (tid == 0) {
                keepm_s = keepm;
                unsigned km = keepm;
                int k2 = s_kept;
                while (km && k2 < NPAD) {
                    int l = __ffs(km) - 1; km &= km - 1;
                    s_keep[k2++] = c * 32 + l;
                }
                s_kept = k2;
            }
        }
        __syncthreads();

        unsigned km = keepm_s;
        if (km) {
            unsigned acc = sup_s[tid];
            while (km) {
                int l = __ffs(km) - 1; km &= km - 1;
                acc |= __ldg(&g_masks[(size_t)(c * 32 + l) * NWORDS + tid]);
            }
            sup_s[tid] = acc;
        }
        int kept = s_kept;
        __syncthreads();           // sup_s/next-chunk ordering + uniform break
        if (kept >= NPAD) break;
    }

    const int nk = s_kept;

    // outputs: boxes (300*4) then scores (300*81); zero-fill invalid rows
    for (int idx = tid; idx < NPAD * 4; idx += 256) {
        int r = idx >> 2, cc = idx & 3;
        float v = 0.0f;
        if (r < nk) {
            float4 b = g_sbox[s_keep[r]];
            v = (cc == 0) ? b.x : (cc == 1) ? b.y : (cc == 2) ? b.z : b.w;
        }
        out[idx] = v;
    }
    for (int idx = tid; idx < NPAD * CLS; idx += 256) {
        int r = idx / CLS, cc = idx - r * CLS;
        float v = 0.0f;
        if (r < nk)
            v = scores[(size_t)g_orig[s_keep[r]] * CLS + cc];
        out[NPAD * 4 + idx] = v;
    }
}

// ---------------------------------------------------------------------------
extern "C" void kernel_launch(void* const* d_in, const int* in_sizes, int n_in,
                              void* d_out, int out_size) {
    const float* meta      = (const float*)d_in[0];
    const float* deltas    = (const float*)d_in[1];
    const float* proposals = (const float*)d_in[2];
    const float* scores    = (const float*)d_in[3];
    float* out = (float*)d_out;

    decode_kernel<<<NBOX / 8, 256>>>(meta, deltas, proposals, scores);

    cudaFuncSetAttribute(rank_kernel,
                         cudaFuncAttributeMaxDynamicSharedMemorySize, 65536);
    rank_kernel<<<256, 256, 65536>>>();

    mask_kernel<<<2048, 256>>>();

    scan_kernel<<<1, 256>>>(scores, out);
}

// round 5
// speedup vs baseline: 7.9022x; 1.1737x over previous
#include <cuda_runtime.h>
#include <cstdint>

#define NBOX   8192
#define CLS    81
#define NPAD   300
#define NWORDS (NBOX / 32)      // 256 words per mask row

// ------------------------- device scratch (static, no allocs) --------------
__device__ float4             g_selv[NBOX];     // decoded boxes (orig order)
__device__ unsigned long long g_key[NBOX];      // composite sort keys
__device__ float4             g_sbox[NBOX];     // boxes in sorted order
__device__ float              g_sarea[NBOX];    // areas in sorted order
__device__ int                g_orig[NBOX];     // sorted pos -> original idx
__device__ unsigned           g_masks[(size_t)NBOX * NWORDS]; // sorted-space IoU>0.5

// ---------------------------------------------------------------------------
// Kernel 1: per-row argmax / max + bbox decode + sort-key build. 1 warp/row.
// ---------------------------------------------------------------------------
__global__ void decode_kernel(const float* __restrict__ meta,
                              const float* __restrict__ deltas,
                              const float* __restrict__ proposals,
                              const float* __restrict__ scores) {
    int row  = (int)((blockIdx.x * blockDim.x + threadIdx.x) >> 5);
    int lane = threadIdx.x & 31;
    if (row >= NBOX) return;

    const float* srow = scores + (size_t)row * CLS;
    float best = -1.0f;
    int   bidx = 0x7FFFFFFF;
    float ms   = -1.0f;
    for (int j = lane; j < CLS; j += 32) {
        float v = srow[j];
        if (v > best) { best = v; bidx = j; }
        if (j >= 1) ms = fmaxf(ms, v);
    }
    #pragma unroll
    for (int off = 16; off; off >>= 1) {
        float ov = __shfl_down_sync(0xffffffffu, best, off);
        int   oi = __shfl_down_sync(0xffffffffu, bidx, off);
        float om = __shfl_down_sync(0xffffffffu, ms,   off);
        if (ov > best || (ov == best && oi < bidx)) { best = ov; bidx = oi; }
        ms = fmaxf(ms, om);
    }

    if (lane == 0) {
        float scale = meta[2];
        const float* p = proposals + (size_t)row * 4;
        float x1 = p[0] / scale, y1 = p[1] / scale;
        float x2 = p[2] / scale, y2 = p[3] / scale;
        float w  = x2 - x1 + 1.0f, h = y2 - y1 + 1.0f;
        float cx = x1 + 0.5f * w,  cy = y1 + 0.5f * h;

        const float* d = deltas + (size_t)row * (4 * CLS) + 4 * bidx;
        float pcx = d[0] * w + cx;
        float pcy = d[1] * h + cy;
        float pw  = expf(d[2]) * w;
        float ph  = expf(d[3]) * h;

        float W1 = meta[1] - 1.0f;
        float H1 = meta[0] - 1.0f;
        float ox1 = fminf(fmaxf(pcx - 0.5f * pw, 0.0f), W1);
        float oy1 = fminf(fmaxf(pcy - 0.5f * ph, 0.0f), H1);
        float ox2 = fminf(fmaxf(pcx + 0.5f * pw, 0.0f), W1);
        float oy2 = fminf(fmaxf(pcy + 0.5f * ph, 0.0f), H1);

        g_selv[row] = make_float4(ox1, oy1, ox2, oy2);
        unsigned int sb = __float_as_uint(ms);   // scores >= 0 -> monotonic bits
        g_key[row] = ((unsigned long long)sb << 13) |
                     (unsigned long long)(8191 - row);   // all keys distinct
    }
}

// ---------------------------------------------------------------------------
// Kernel 2: rank-by-counting + scatter into sorted order. 256 blocks.
// ---------------------------------------------------------------------------
__global__ void __launch_bounds__(256)
rank_kernel() {
    extern __shared__ unsigned long long keys[];   // 64 KB
    const int tid = threadIdx.x;
    for (int i = tid; i < NBOX; i += 256) keys[i] = g_key[i];
    __syncthreads();

    const int warp = tid >> 5, lane = tid & 31;
    const int row0 = blockIdx.x * 32 + warp * 4;

    unsigned long long rk0 = keys[row0 + 0];
    unsigned long long rk1 = keys[row0 + 1];
    unsigned long long rk2 = keys[row0 + 2];
    unsigned long long rk3 = keys[row0 + 3];
    int c0 = 0, c1 = 0, c2 = 0, c3 = 0;

    #pragma unroll 4
    for (int c = lane; c < NBOX; c += 32) {
        unsigned long long kc = keys[c];
        c0 += (kc > rk0);
        c1 += (kc > rk1);
        c2 += (kc > rk2);
        c3 += (kc > rk3);
    }
    #pragma unroll
    for (int off = 16; off; off >>= 1) {
        c0 += __shfl_down_sync(0xffffffffu, c0, off);
        c1 += __shfl_down_sync(0xffffffffu, c1, off);
        c2 += __shfl_down_sync(0xffffffffu, c2, off);
        c3 += __shfl_down_sync(0xffffffffu, c3, off);
    }
    if (lane == 0) {
        int rr[4] = {c0, c1, c2, c3};
        #pragma unroll
        for (int q = 0; q < 4; q++) {
            int i = row0 + q, r = rr[q];
            float4 b = g_selv[i];
            g_sbox[r]  = b;
            g_sarea[r] = fmaxf(b.z - b.x, 0.0f) * fmaxf(b.w - b.y, 0.0f);
            g_orig[r]  = i;
        }
    }
}

// ---------------------------------------------------------------------------
// Kernel 3: sorted-space IoU>0.5 bitmask, upper triangle only.
// ---------------------------------------------------------------------------
__global__ void __launch_bounds__(256)
mask_kernel() {
    __shared__ float4 rbs[32];
    __shared__ float  ras[32];
    __shared__ float4 cbT[32 * 33];
    __shared__ float  caT[32 * 33];

    const int m  = blockIdx.x;
    const int rb = m & 255;
    const int cb = m >> 8;
    if (cb < (rb >> 5)) return;

    const int rowbase = rb * 32;
    const int colbase = cb * 1024;
    const int tid = threadIdx.x;

    if (tid < 32) {
        rbs[tid] = g_sbox[rowbase + tid];
        ras[tid] = g_sarea[rowbase + tid];
    }
    for (int jj = tid; jj < 1024; jj += 256) {
        int w = jj >> 5, bb = jj & 31;
        cbT[bb * 33 + w] = g_sbox[colbase + jj];
        caT[bb * 33 + w] = g_sarea[colbase + jj];
    }
    __syncthreads();

    const int r0 = tid >> 5;
    const int w  = tid & 31;
    float4 bi[4];
    float  si[4];
    #pragma unroll
    for (int k = 0; k < 4; k++) {
        bi[k] = rbs[r0 + 8 * k];
        si[k] = ras[r0 + 8 * k] + 1e-8f;
    }
    unsigned bits0 = 0, bits1 = 0, bits2 = 0, bits3 = 0;

    #pragma unroll
    for (int b = 0; b < 32; b++) {
        float4 bj = cbT[b * 33 + w];
        float  aj = caT[b * 33 + w];
        #pragma unroll
        for (int k = 0; k < 4; k++) {
            float xx1 = fmaxf(bi[k].x, bj.x), yy1 = fmaxf(bi[k].y, bj.y);
            float xx2 = fminf(bi[k].z, bj.z), yy2 = fminf(bi[k].w, bj.w);
            float iw  = fmaxf(xx2 - xx1, 0.0f);
            float ih  = fmaxf(yy2 - yy1, 0.0f);
            float inter = iw * ih;
            unsigned p = (3.0f * inter > si[k] + aj) ? (1u << b) : 0u;
            if (k == 0) bits0 |= p;
            else if (k == 1) bits1 |= p;
            else if (k == 2) bits2 |= p;
            else bits3 |= p;
        }
    }
    size_t base = (size_t)rowbase * NWORDS + (size_t)cb * 32 + w;
    g_masks[base + (size_t)(r0 +  0) * NWORDS] = bits0;
    g_masks[base + (size_t)(r0 +  8) * NWORDS] = bits1;
    g_masks[base + (size_t)(r0 + 16) * NWORDS] = bits2;
    g_masks[base + (size_t)(r0 + 24) * NWORDS] = bits3;
}

// ---------------------------------------------------------------------------
// Kernel 4: pipelined greedy scan (1 block, 256 threads) + output.
//   - conf + next-word prefetched one chunk ahead (static addresses)
//   - keeps' contribution to word c+1 via register shfl-OR (zero latency)
//   - full-row suppression OR lags one chunk (latency hidden); one bar/chunk
// ---------------------------------------------------------------------------
__global__ void __launch_bounds__(256)
scan_kernel(const float* __restrict__ scores, float* __restrict__ out) {
    __shared__ unsigned sup_s[NWORDS];   // suppression bits, sorted space
    __shared__ unsigned kbuf[2];         // double-buffered keep mask
    __shared__ int      kcnt[2];         // double-buffered kept count
    __shared__ int      s_keep[NPAD];

    const int tid = threadIdx.x;
    sup_s[tid] = 0u;
    if (tid == 0) { kbuf[0] = kbuf[1] = 0u; kcnt[0] = kcnt[1] = 0; }
    __syncthreads();

    volatile unsigned* vsup = sup_s;

    // preload chunk 0 state (static addresses)
    unsigned conf = 0, nextw = 0, supfix = 0;
    if (tid < 32) {
        conf  = __ldg(&g_masks[(size_t)tid * NWORDS + 0]);
        nextw = __ldg(&g_masks[(size_t)tid * NWORDS + 1]);
    }

    int nk = 0;
    for (int c = 0; c < NWORDS; c++) {
        // ---- background: apply chunk c-1's keeps to this thread's word ----
        unsigned bacc = 0u;
        if (c > 0) {
            unsigned t = kbuf[(c - 1) & 1];
            const int prevbase = (c - 1) * 32;
            while (t) {
                int l = __ffs(t) - 1; t &= t - 1;
                bacc |= __ldg(&g_masks[(size_t)(prevbase + l) * NWORDS + tid]);
            }
        }

        if (tid < 32) {
            // prefetch chunk c+1 (static addresses; overlaps this chunk)
            unsigned conf_n = 0, nextw_n = 0;
            if (c + 1 < NWORDS) {
                const unsigned* rown =
                    &g_masks[(size_t)((c + 1) * 32 + tid) * NWORDS];
                conf_n = __ldg(&rown[c + 1]);
                int w2 = (c + 2 < NWORDS) ? (c + 2) : (NWORDS - 1);
                nextw_n = __ldg(&rown[w2]);
            }

            // availability: lagged sup word + register fast-correction
            unsigned avail = ~(vsup[c] | supfix);
            unsigned am = avail, keepm = 0;
            while (am) {
                int l = __ffs(am) - 1;
                keepm |= 1u << l;
                unsigned cl = __shfl_sync(0xffffffffu, conf, l);
                am &= ~cl;
                am &= ~(1u << l);
            }

            // fast path: this chunk's keeps -> next availability word
            unsigned v = ((keepm >> tid) & 1u) ? nextw : 0u;
            #pragma unroll
            for (int off = 16; off; off >>= 1)
                v |= __shfl_xor_sync(0xffffffffu, v, off);
            supfix = v;
            conf  = conf_n;
            nextw = nextw_n;

            if (tid == 0) {
                kbuf[c & 1] = keepm;
                int k2 = nk;
                unsigned km = keepm;
                while (km && k2 < NPAD) {
                    int l = __ffs(km) - 1; km &= km - 1;
                    s_keep[k2++] = c * 32 + l;
                }
                kcnt[c & 1] = k2;
            }
        }

        if (bacc) vsup[tid] |= bacc;     // owner-thread RMW; races benign
        __syncthreads();
        nk = kcnt[c & 1];                // uniform (double-buffered)
        if (nk >= NPAD) break;
    }

    // ---- outputs: boxes (300*4) then scores (300*81); zero invalid rows ----
    for (int idx = tid; idx < NPAD * 4; idx += 256) {
        int r = idx >> 2, cc = idx & 3;
        float v = 0.0f;
        if (r < nk) {
            float4 b = g_sbox[s_keep[r]];
            v = (cc == 0) ? b.x : (cc == 1) ? b.y : (cc == 2) ? b.z : b.w;
        }
        out[idx] = v;
    }
    for (int idx = tid; idx < NPAD * CLS; idx += 256) {
        int r = idx / CLS, cc = idx - r * CLS;
        float v = 0.0f;
        if (r < nk)
            v = scores[(size_t)g_orig[s_keep[r]] * CLS + cc];
        out[NPAD * 4 + idx] = v;
    }
}

// ---------------------------------------------------------------------------
extern "C" void kernel_launch(void* const* d_in, const int* in_sizes, int n_in,
                              void* d_out, int out_size) {
    const float* meta      = (const float*)d_in[0];
    const float* deltas    = (const float*)d_in[1];
    const float* proposals = (const float*)d_in[2];
    const float* scores    = (const float*)d_in[3];
    float* out = (float*)d_out;

    decode_kernel<<<NBOX / 8, 256>>>(meta, deltas, proposals, scores);

    cudaFuncSetAttribute(rank_kernel,
                         cudaFuncAttributeMaxDynamicSharedMemorySize, 65536);
    rank_kernel<<<256, 256, 65536>>>();

    mask_kernel<<<2048, 256>>>();

    scan_kernel<<<1, 256>>>(scores, out);
}